// round 10
// baseline (speedup 1.0000x reference)
#include <cuda_runtime.h>
#include <cuda_bf16.h>
#include <cuda_fp16.h>
#include <cstdint>
#include <cstddef>

// ============================================================================
// AutoregressiveGRU on GB300 — sm_103 base target, HMMA mma.sync m16n8k16.
//
// fp16 2-term scheme: acc += Ah*Bh ; acc2 += Ah*(Bl*2048); res = acc+acc2/2048.
// One fused GEMM [256,1024]x[1024,4096] per step (z|r|xh|uh packed per d).
//
// R7 vs R6 (latency-bound, issue 18%, 2 warps/SMSP):
//  - 512 threads / 16 warps per CTA (4 warps/SMSP), warp tile 32x16
//  - same CTA tile 64x128, same smem, same global traffic
// ============================================================================

#define DD 1024
#define BATCH 256
#define TSTEPS 128
#define NPACK 4096

#define CTA_M 64
#define CTA_N 128
#define KC 64            // K per chunk (64 fp16 = 128 B/row)
#define KCH 16           // 1024 / 64
#define STAGES 4
#define A_TILE_B (CTA_M * 128)            // 8192
#define B_TILE_B (CTA_N * 128)            // 16384
#define STAGE_BYTES (A_TILE_B + 2 * B_TILE_B)       // 40960
#define SMEM_DYN (STAGES * STAGE_BYTES)             // 163840

// ---------------- device globals --------------------------------------------
__device__ __half g_Wmh[NPACK * DD];     // main weights hi
__device__ __half g_Wml[NPACK * DD];     // main weights (lo * 2048)
__device__ __half g_W1h[NPACK * DD];     // step-1 weights hi
__device__ __half g_W1l[NPACK * DD];     // step-1 weights (lo * 2048)
__device__ __half g_h16[2][BATCH * DD];  // fp16 state (GEMM A operand), ping-pong
__device__ float g_hstate[BATCH * DD];   // fp32 state (epilogue hold)
__device__ float g_bias[NPACK];

// ---------------- PTX helpers -----------------------------------------------
__device__ __forceinline__ uint32_t smem_u32(const void* p) {
    uint32_t a;
    asm("{ .reg .u64 t; cvta.to.shared.u64 t, %1; cvt.u32.u64 %0, t; }" : "=r"(a) : "l"(p));
    return a;
}
__device__ __forceinline__ void cp16(uint32_t dst, const void* src) {
    asm volatile("cp.async.cg.shared.global [%0], [%1], 16;" :: "r"(dst), "l"(src) : "memory");
}
__device__ __forceinline__ void cp_commit() {
    asm volatile("cp.async.commit_group;" ::: "memory");
}
template <int N>
__device__ __forceinline__ void cp_wait() {
    asm volatile("cp.async.wait_group %0;" :: "n"(N) : "memory");
}
__device__ __forceinline__ void ldsm_x4(uint32_t* r, uint32_t addr) {
    asm volatile("ldmatrix.sync.aligned.m8n8.x4.shared.b16 {%0,%1,%2,%3}, [%4];"
                 : "=r"(r[0]), "=r"(r[1]), "=r"(r[2]), "=r"(r[3]) : "r"(addr));
}
__device__ __forceinline__ void mma_f16(float* c, const uint32_t* a, uint32_t b0, uint32_t b1) {
    asm volatile("mma.sync.aligned.m16n8k16.row.col.f32.f16.f16.f32 "
                 "{%0,%1,%2,%3}, {%4,%5,%6,%7}, {%8,%9}, {%0,%1,%2,%3};"
                 : "+f"(c[0]), "+f"(c[1]), "+f"(c[2]), "+f"(c[3])
                 : "r"(a[0]), "r"(a[1]), "r"(a[2]), "r"(a[3]), "r"(b0), "r"(b1));
}

// ---------------- step kernel ------------------------------------------------
__global__ __launch_bounds__(512, 1) void gru_step_kernel(
    const __half* __restrict__ Whi, const __half* __restrict__ Wlo,
    const __half* __restrict__ h16_in, __half* __restrict__ h16_out,
    float* __restrict__ hstate,
    const float* __restrict__ bias, float* __restrict__ out, int t)
{
    extern __shared__ __align__(128) char smem_raw[];
    const uint32_t sbase = smem_u32(smem_raw);
    const int tid = threadIdx.x;
    const int wid = tid >> 5, lane = tid & 31;
    const int ctan = blockIdx.x;   // 0..31
    const int ctam = blockIdx.y;   // 0..3

    const int wm = wid & 1;        // 0..1 : 32-row warp block
    const int wn = wid >> 1;       // 0..7 : 16-col warp block

    const __half* Ag = h16_in + (size_t)ctam * CTA_M * DD;
    const __half* Bh = Whi + (size_t)ctan * CTA_N * DD;
    const __half* Bl = Wlo + (size_t)ctan * CTA_N * DD;

    // issue one slice of a chunk's loads. part 0: A, part 1: Bh, part 2: Bl.
    auto issue_part = [&](int slot, int k0, int part) {
        uint32_t base = sbase + (uint32_t)slot * STAGE_BYTES;
        if (part == 0) {
            int row = tid >> 3, grp = tid & 7;   // 512 thr = 64 rows x 8 grp
            uint32_t sw = (uint32_t)(row * 128) + (uint32_t)((grp ^ (row & 7)) << 4);
            cp16(base + sw, Ag + (size_t)row * DD + k0 + grp * 8);
        } else {
            uint32_t tb = base + A_TILE_B + (uint32_t)(part - 1) * B_TILE_B;
            const __half* src = (part == 1) ? Bh : Bl;
#pragma unroll
            for (int it = 0; it < 2; ++it) {
                int idx = tid + it * 512;
                int row = idx >> 3, grp = idx & 7;
                uint32_t sw = (uint32_t)(row * 128) + (uint32_t)((grp ^ (row & 7)) << 4);
                cp16(tb + sw, src + (size_t)row * DD + k0 + grp * 8);
            }
        }
    };
    auto issue_chunk = [&](int slot, int k0) {
        issue_part(slot, k0, 0); issue_part(slot, k0, 1); issue_part(slot, k0, 2);
        cp_commit();
    };

    float acc[2][2][4], acc2[2][2][4];
#pragma unroll
    for (int i = 0; i < 2; ++i)
#pragma unroll
        for (int j = 0; j < 2; ++j)
#pragma unroll
            for (int k = 0; k < 4; ++k) { acc[i][j][k] = 0.0f; acc2[i][j][k] = 0.0f; }

    // prologue: chunks 0..2 in flight
    issue_chunk(0, 0);
    issue_chunk(1, KC);
    issue_chunk(2, 2 * KC);

    // ldmatrix per-lane constants
    const int arow = wm * 32 + (lane & 15);
    const int agl = (lane >> 4);
    const int brow = wn * 16 + (lane & 7) + ((lane >> 4) & 1) * 8;
    const int bgl = (lane >> 3) & 1;

    // double-buffered fragments
    uint32_t fa[2][2][4], fbh[2][4], fbl[2][4];

#define LOAD_FRAGS(b, baseA, baseBH, baseBL, kk_) do {                               \
    _Pragma("unroll")                                                                \
    for (int mt = 0; mt < 2; ++mt) {                                                 \
        int row = arow + mt * 16;                                                    \
        uint32_t off = (uint32_t)(row * 128) +                                       \
                       (uint32_t)(((((kk_) * 2) + agl) ^ (row & 7)) << 4);           \
        ldsm_x4(fa[b][mt], (baseA) + off);                                           \
    }                                                                                \
    {                                                                                \
        int n = brow;                                                                \
        uint32_t off = (uint32_t)(n * 128) +                                         \
                       (uint32_t)(((((kk_) * 2) + bgl) ^ (n & 7)) << 4);             \
        ldsm_x4(fbh[b], (baseBH) + off);                                             \
        ldsm_x4(fbl[b], (baseBL) + off);                                             \
    }                                                                                \
} while (0)

#define DO_MMAS(b) do {                                                              \
    _Pragma("unroll")                                                                \
    for (int mt = 0; mt < 2; ++mt)                                                   \
        _Pragma("unroll")                                                            \
        for (int nb = 0; nb < 2; ++nb) {                                             \
            int hf = nb * 2;                                                         \
            mma_f16(acc[mt][nb], fa[b][mt], fbh[b][hf], fbh[b][hf + 1]);             \
        }                                                                            \
    _Pragma("unroll")                                                                \
    for (int mt = 0; mt < 2; ++mt)                                                   \
        _Pragma("unroll")                                                            \
        for (int nb = 0; nb < 2; ++nb) {                                             \
            int hf = nb * 2;                                                         \
            mma_f16(acc2[mt][nb], fa[b][mt], fbl[b][hf], fbl[b][hf + 1]);            \
        }                                                                            \
} while (0)

    for (int i = 0; i < KCH; ++i) {
        cp_wait<2>();
        __syncthreads();
        uint32_t base = sbase + (uint32_t)(i & (STAGES - 1)) * STAGE_BYTES;
        const uint32_t aB = base;
        const uint32_t bhB = base + A_TILE_B, blB = bhB + B_TILE_B;
        const int pf = i + 3;
        const int pslot = pf & (STAGES - 1);
        const int pk0 = pf * KC;

        LOAD_FRAGS(0, aB, bhB, blB, 0);
#pragma unroll
        for (int kk = 0; kk < 4; ++kk) {
            if (kk < 3) {
                LOAD_FRAGS((kk + 1) & 1, aB, bhB, blB, kk + 1);
                if (pf < KCH) issue_part(pslot, pk0, kk);
            } else {
                cp_commit();
            }
            DO_MMAS(kk & 1);
        }
    }
#undef LOAD_FRAGS
#undef DO_MMAS

    // ---- epilogue through SMEM ----
    __syncthreads();
    float* es = (float*)smem_raw;   // 64 x 128 fp32 = 32 KB
    {
        const float s = 1.0f / 2048.0f;
        const int r0 = wm * 32 + (lane >> 2);
        const int c0 = wn * 16 + (lane & 3) * 2;
#pragma unroll
        for (int mt = 0; mt < 2; ++mt)
#pragma unroll
            for (int nb = 0; nb < 2; ++nb) {
                int r = r0 + mt * 16, c = c0 + nb * 8;
                *(float2*)&es[r * 128 + c] =
                    make_float2(acc[mt][nb][0] + acc2[mt][nb][0] * s,
                                acc[mt][nb][1] + acc2[mt][nb][1] * s);
                *(float2*)&es[(r + 8) * 128 + c] =
                    make_float2(acc[mt][nb][2] + acc2[mt][nb][2] * s,
                                acc[mt][nb][3] + acc2[mt][nb][3] * s);
            }
    }
    __syncthreads();

#pragma unroll
    for (int p = 0; p < 4; ++p) {
        int linear = p * 512 + tid;              // 0..2047
        int m = linear >> 5;                     // 0..63
        int dloc = linear & 31;                  // 0..31
        float4 v = *(float4*)&es[m * 128 + dloc * 4];
        float4 bb = __ldg((const float4*)(bias + ctan * 128 + dloc * 4));
        float vz = v.x + bb.x;
        float vr = v.y + bb.y;
        float vh = v.z + bb.z;
        float vu = v.w + bb.w;
        float z = 1.0f / (1.0f + __expf(-vz));
        float r = 1.0f / (1.0f + __expf(-vr));
        float hh = tanhf(vh + r * vu);
        int gm = ctam * CTA_M + m;
        int d = ctan * 32 + dloc;
        size_t hidx = (size_t)gm * DD + d;
        float hold = hstate[hidx];
        float hn = z * hold + (1.0f - z) * hh;
        out[(size_t)gm * (TSTEPS * DD) + (size_t)t * DD + d] = hn;
        hstate[hidx] = hn;
        h16_out[hidx] = __float2half_rn(hn);
    }
}

// ---------------- pack / init kernels ---------------------------------------
__global__ void pack_weights(const float* __restrict__ W, const float* __restrict__ U,
                             const float* __restrict__ b,
                             __half* __restrict__ Wmh, __half* __restrict__ Wml,
                             __half* __restrict__ W1h, __half* __restrict__ W1l,
                             float* __restrict__ bp)
{
    int idx = blockIdx.x * blockDim.x + threadIdx.x;
    if (idx >= NPACK * DD) return;
    int c = idx >> 10;          // packed column (d*4 + gate)
    int k = idx & 1023;
    int d = c >> 2, g = c & 3;
    const int TD = 3 * DD;
    float vm, v1;
    if (g == 0)      { float u = U[(size_t)k * TD + d];            vm = W[(size_t)k * TD + d] + u;            v1 = u; }
    else if (g == 1) { float u = U[(size_t)k * TD + DD + d];       vm = W[(size_t)k * TD + DD + d] + u;       v1 = u; }
    else if (g == 2) { vm = W[(size_t)k * TD + 2 * DD + d];        v1 = 0.0f; }
    else             { float u = U[(size_t)k * TD + 2 * DD + d];   vm = u;    v1 = u; }
    __half h1 = __float2half_rn(vm);
    Wmh[idx] = h1;
    Wml[idx] = __float2half_rn((vm - __half2float(h1)) * 2048.0f);
    __half h2 = __float2half_rn(v1);
    W1h[idx] = h2;
    W1l[idx] = __float2half_rn((v1 - __half2float(h2)) * 2048.0f);
    if (k == 0)
        bp[c] = (g == 0) ? b[d] : (g == 1) ? b[DD + d] : (g == 2) ? b[2 * DD + d] : 0.0f;
}

__global__ void init_h(const float* __restrict__ x,
                       __half* __restrict__ h16, float* __restrict__ hstate)
{
    int i = blockIdx.x * blockDim.x + threadIdx.x;
    if (i < BATCH * DD) {
        float v = x[i];
        h16[i] = __float2half_rn(v);
        hstate[i] = v;
    }
}

// ---------------- launch -----------------------------------------------------
extern "C" void kernel_launch(void* const* d_in, const int* in_sizes, int n_in,
                              void* d_out, int out_size)
{
    const float* x = (const float*)d_in[0];
    const float* W = (const float*)d_in[1];
    const float* U = (const float*)d_in[2];
    const float* b = (const float*)d_in[3];
    float* out = (float*)d_out;

    void *pWmh, *pWml, *pW1h, *pW1l, *pH16, *pHst, *pBias;
    cudaGetSymbolAddress(&pWmh, g_Wmh);
    cudaGetSymbolAddress(&pWml, g_Wml);
    cudaGetSymbolAddress(&pW1h, g_W1h);
    cudaGetSymbolAddress(&pW1l, g_W1l);
    cudaGetSymbolAddress(&pH16, g_h16);
    cudaGetSymbolAddress(&pHst, g_hstate);
    cudaGetSymbolAddress(&pBias, g_bias);
    __half* Wmh = (__half*)pWmh;
    __half* Wml = (__half*)pWml;
    __half* W1h = (__half*)pW1h;
    __half* W1l = (__half*)pW1l;
    __half* H16 = (__half*)pH16;     // [2][BATCH*DD]
    float* Hst = (float*)pHst;
    float* Bias = (float*)pBias;

    cudaFuncSetAttribute(gru_step_kernel, cudaFuncAttributeMaxDynamicSharedMemorySize, SMEM_DYN);

    pack_weights<<<(NPACK * DD + 255) / 256, 256>>>(W, U, b, Wmh, Wml, W1h, W1l, Bias);
    init_h<<<(BATCH * DD + 255) / 256, 256>>>(x, H16, Hst);

    dim3 grid(32, 4);
    for (int t = 0; t < TSTEPS; ++t) {
        const __half* wh = (t == 0) ? W1h : Wmh;
        const __half* wl = (t == 0) ? W1l : Wml;
        int bin = t & 1, bout = (t + 1) & 1;
        gru_step_kernel<<<grid, 512, SMEM_DYN>>>(
            wh, wl,
            H16 + (size_t)bin * (BATCH * DD), H16 + (size_t)bout * (BATCH * DD),
            Hst, Bias, out, t);
    }
    (void)in_sizes; (void)n_in; (void)out_size;
}

// round 11
// speedup vs baseline: 1.0636x; 1.0636x over previous
#include <cuda_runtime.h>
#include <cuda_bf16.h>
#include <cuda_fp16.h>
#include <cstdint>
#include <cstddef>

// ============================================================================
// AutoregressiveGRU on GB300 — sm_103 base target, HMMA mma.sync m16n8k16.
//
// fp16 2-term scheme: acc += Ah*Bh ; acc2 += Ah*(Bl*2048); res = acc+acc2/2048.
// One fused GEMM [256,1024]x[1024,4096] per step (z|r|xh|uh packed per d).
//
// R11 vs R10 (phase-serialization theory: crossbar+tensor alternate, time=sum):
//  - hand-interleaved inner body: LDSM(kk+1) scattered 1:2 between MMA(kk)
//  - everything else identical (512 thr, warp tile 32x16, 4 stages)
// ============================================================================

#define DD 1024
#define BATCH 256
#define TSTEPS 128
#define NPACK 4096

#define CTA_M 64
#define CTA_N 128
#define KC 64            // K per chunk (64 fp16 = 128 B/row)
#define KCH 16           // 1024 / 64
#define STAGES 4
#define A_TILE_B (CTA_M * 128)            // 8192
#define B_TILE_B (CTA_N * 128)            // 16384
#define STAGE_BYTES (A_TILE_B + 2 * B_TILE_B)       // 40960
#define SMEM_DYN (STAGES * STAGE_BYTES)             // 163840

// ---------------- device globals --------------------------------------------
__device__ __half g_Wmh[NPACK * DD];     // main weights hi
__device__ __half g_Wml[NPACK * DD];     // main weights (lo * 2048)
__device__ __half g_W1h[NPACK * DD];     // step-1 weights hi
__device__ __half g_W1l[NPACK * DD];     // step-1 weights (lo * 2048)
__device__ __half g_h16[2][BATCH * DD];  // fp16 state (GEMM A operand), ping-pong
__device__ float g_hstate[BATCH * DD];   // fp32 state (epilogue hold)
__device__ float g_bias[NPACK];

// ---------------- PTX helpers -----------------------------------------------
__device__ __forceinline__ uint32_t smem_u32(const void* p) {
    uint32_t a;
    asm("{ .reg .u64 t; cvta.to.shared.u64 t, %1; cvt.u32.u64 %0, t; }" : "=r"(a) : "l"(p));
    return a;
}
__device__ __forceinline__ void cp16(uint32_t dst, const void* src) {
    asm volatile("cp.async.cg.shared.global [%0], [%1], 16;" :: "r"(dst), "l"(src) : "memory");
}
__device__ __forceinline__ void cp_commit() {
    asm volatile("cp.async.commit_group;" ::: "memory");
}
template <int N>
__device__ __forceinline__ void cp_wait() {
    asm volatile("cp.async.wait_group %0;" :: "n"(N) : "memory");
}
__device__ __forceinline__ void ldsm_x4(uint32_t* r, uint32_t addr) {
    asm volatile("ldmatrix.sync.aligned.m8n8.x4.shared.b16 {%0,%1,%2,%3}, [%4];"
                 : "=r"(r[0]), "=r"(r[1]), "=r"(r[2]), "=r"(r[3]) : "r"(addr));
}
__device__ __forceinline__ void mma_f16(float* c, const uint32_t* a, uint32_t b0, uint32_t b1) {
    asm volatile("mma.sync.aligned.m16n8k16.row.col.f32.f16.f16.f32 "
                 "{%0,%1,%2,%3}, {%4,%5,%6,%7}, {%8,%9}, {%0,%1,%2,%3};"
                 : "+f"(c[0]), "+f"(c[1]), "+f"(c[2]), "+f"(c[3])
                 : "r"(a[0]), "r"(a[1]), "r"(a[2]), "r"(a[3]), "r"(b0), "r"(b1));
}

// ---------------- step kernel ------------------------------------------------
__global__ __launch_bounds__(512, 1) void gru_step_kernel(
    const __half* __restrict__ Whi, const __half* __restrict__ Wlo,
    const __half* __restrict__ h16_in, __half* __restrict__ h16_out,
    float* __restrict__ hstate,
    const float* __restrict__ bias, float* __restrict__ out, int t)
{
    extern __shared__ __align__(128) char smem_raw[];
    const uint32_t sbase = smem_u32(smem_raw);
    const int tid = threadIdx.x;
    const int wid = tid >> 5, lane = tid & 31;
    const int ctan = blockIdx.x;   // 0..31
    const int ctam = blockIdx.y;   // 0..3

    const int wm = wid & 1;        // 0..1 : 32-row warp block
    const int wn = wid >> 1;       // 0..7 : 16-col warp block

    const __half* Ag = h16_in + (size_t)ctam * CTA_M * DD;
    const __half* Bh = Whi + (size_t)ctan * CTA_N * DD;
    const __half* Bl = Wlo + (size_t)ctan * CTA_N * DD;

    // issue one slice of a chunk's loads. part 0: A, part 1: Bh, part 2: Bl.
    auto issue_part = [&](int slot, int k0, int part) {
        uint32_t base = sbase + (uint32_t)slot * STAGE_BYTES;
        if (part == 0) {
            int row = tid >> 3, grp = tid & 7;   // 512 thr = 64 rows x 8 grp
            uint32_t sw = (uint32_t)(row * 128) + (uint32_t)((grp ^ (row & 7)) << 4);
            cp16(base + sw, Ag + (size_t)row * DD + k0 + grp * 8);
        } else {
            uint32_t tb = base + A_TILE_B + (uint32_t)(part - 1) * B_TILE_B;
            const __half* src = (part == 1) ? Bh : Bl;
#pragma unroll
            for (int it = 0; it < 2; ++it) {
                int idx = tid + it * 512;
                int row = idx >> 3, grp = idx & 7;
                uint32_t sw = (uint32_t)(row * 128) + (uint32_t)((grp ^ (row & 7)) << 4);
                cp16(tb + sw, src + (size_t)row * DD + k0 + grp * 8);
            }
        }
    };
    auto issue_chunk = [&](int slot, int k0) {
        issue_part(slot, k0, 0); issue_part(slot, k0, 1); issue_part(slot, k0, 2);
        cp_commit();
    };

    float acc[2][2][4], acc2[2][2][4];
#pragma unroll
    for (int i = 0; i < 2; ++i)
#pragma unroll
        for (int j = 0; j < 2; ++j)
#pragma unroll
            for (int k = 0; k < 4; ++k) { acc[i][j][k] = 0.0f; acc2[i][j][k] = 0.0f; }

    // prologue: chunks 0..2 in flight
    issue_chunk(0, 0);
    issue_chunk(1, KC);
    issue_chunk(2, 2 * KC);

    // ldmatrix per-lane constants
    const int arow = wm * 32 + (lane & 15);
    const int agl = (lane >> 4);
    const int brow = wn * 16 + (lane & 7) + ((lane >> 4) & 1) * 8;
    const int bgl = (lane >> 3) & 1;

    // double-buffered fragments
    uint32_t fa[2][2][4], fbh[2][4], fbl[2][4];

    // individual LDSM pieces (buffer b, k-subtile kk_)
#define LDSM_A(b, mt, kk_) do {                                                      \
    int row_ = arow + (mt) * 16;                                                     \
    uint32_t off_ = (uint32_t)(row_ * 128) +                                         \
                    (uint32_t)(((((kk_) * 2) + agl) ^ (row_ & 7)) << 4);             \
    ldsm_x4(fa[b][mt], aB + off_);                                                   \
} while (0)
#define LDSM_BH(b, kk_) do {                                                         \
    uint32_t off_ = (uint32_t)(brow * 128) +                                         \
                    (uint32_t)(((((kk_) * 2) + bgl) ^ (brow & 7)) << 4);             \
    ldsm_x4(fbh[b], bhB + off_);                                                     \
} while (0)
#define LDSM_BL(b, kk_) do {                                                         \
    uint32_t off_ = (uint32_t)(brow * 128) +                                         \
                    (uint32_t)(((((kk_) * 2) + bgl) ^ (brow & 7)) << 4);             \
    ldsm_x4(fbl[b], blB + off_);                                                     \
} while (0)

    // interleaved body: 8 MMAs of buffer bc + (optionally) 4 LDSMs into bn for kkn.
    // LDSM:MMA mix 1:2 so crossbar and tensor pipes stay concurrently fed even
    // when warps are phase-locked by the chunk barrier.
#define KK_BODY(bc, bn, kkn, do_ld) do {                                             \
    if (do_ld) LDSM_A(bn, 0, kkn);                                                   \
    mma_f16(acc[0][0],  fa[bc][0], fbh[bc][0], fbh[bc][1]);                          \
    mma_f16(acc[0][1],  fa[bc][0], fbh[bc][2], fbh[bc][3]);                          \
    if (do_ld) LDSM_BH(bn, kkn);                                                     \
    mma_f16(acc2[0][0], fa[bc][0], fbl[bc][0], fbl[bc][1]);                          \
    mma_f16(acc2[0][1], fa[bc][0], fbl[bc][2], fbl[bc][3]);                          \
    if (do_ld) LDSM_A(bn, 1, kkn);                                                   \
    mma_f16(acc[1][0],  fa[bc][1], fbh[bc][0], fbh[bc][1]);                          \
    mma_f16(acc[1][1],  fa[bc][1], fbh[bc][2], fbh[bc][3]);                          \
    if (do_ld) LDSM_BL(bn, kkn);                                                     \
    mma_f16(acc2[1][0], fa[bc][1], fbl[bc][0], fbl[bc][1]);                          \
    mma_f16(acc2[1][1], fa[bc][1], fbl[bc][2], fbl[bc][3]);                          \
} while (0)

    for (int i = 0; i < KCH; ++i) {
        cp_wait<2>();
        __syncthreads();
        uint32_t base = sbase + (uint32_t)(i & (STAGES - 1)) * STAGE_BYTES;
        const uint32_t aB = base;
        const uint32_t bhB = base + A_TILE_B, blB = bhB + B_TILE_B;
        const int pf = i + 3;
        const int pslot = pf & (STAGES - 1);
        const int pk0 = pf * KC;
        const bool pfv = (pf < KCH);

        // kk=0 fragments
        LDSM_A(0, 0, 0); LDSM_BH(0, 0); LDSM_A(0, 1, 0); LDSM_BL(0, 0);

        KK_BODY(0, 1, 1, true);
        if (pfv) issue_part(pslot, pk0, 0);
        KK_BODY(1, 0, 2, true);
        if (pfv) issue_part(pslot, pk0, 1);
        KK_BODY(0, 1, 3, true);
        if (pfv) issue_part(pslot, pk0, 2);
        cp_commit();
        KK_BODY(1, 0, 0, false);
    }
#undef KK_BODY
#undef LDSM_A
#undef LDSM_BH
#undef LDSM_BL

    // ---- epilogue through SMEM ----
    __syncthreads();
    float* es = (float*)smem_raw;   // 64 x 128 fp32 = 32 KB
    {
        const float s = 1.0f / 2048.0f;
        const int r0 = wm * 32 + (lane >> 2);
        const int c0 = wn * 16 + (lane & 3) * 2;
#pragma unroll
        for (int mt = 0; mt < 2; ++mt)
#pragma unroll
            for (int nb = 0; nb < 2; ++nb) {
                int r = r0 + mt * 16, c = c0 + nb * 8;
                *(float2*)&es[r * 128 + c] =
                    make_float2(acc[mt][nb][0] + acc2[mt][nb][0] * s,
                                acc[mt][nb][1] + acc2[mt][nb][1] * s);
                *(float2*)&es[(r + 8) * 128 + c] =
                    make_float2(acc[mt][nb][2] + acc2[mt][nb][2] * s,
                                acc[mt][nb][3] + acc2[mt][nb][3] * s);
            }
    }
    __syncthreads();

#pragma unroll
    for (int p = 0; p < 4; ++p) {
        int linear = p * 512 + tid;              // 0..2047
        int m = linear >> 5;                     // 0..63
        int dloc = linear & 31;                  // 0..31
        float4 v = *(float4*)&es[m * 128 + dloc * 4];
        float4 bb = __ldg((const float4*)(bias + ctan * 128 + dloc * 4));
        float vz = v.x + bb.x;
        float vr = v.y + bb.y;
        float vh = v.z + bb.z;
        float vu = v.w + bb.w;
        float z = 1.0f / (1.0f + __expf(-vz));
        float r = 1.0f / (1.0f + __expf(-vr));
        float hh = tanhf(vh + r * vu);
        int gm = ctam * CTA_M + m;
        int d = ctan * 32 + dloc;
        size_t hidx = (size_t)gm * DD + d;
        float hold = hstate[hidx];
        float hn = z * hold + (1.0f - z) * hh;
        out[(size_t)gm * (TSTEPS * DD) + (size_t)t * DD + d] = hn;
        hstate[hidx] = hn;
        h16_out[hidx] = __float2half_rn(hn);
    }
}

// ---------------- pack / init kernels ---------------------------------------
__global__ void pack_weights(const float* __restrict__ W, const float* __restrict__ U,
                             const float* __restrict__ b,
                             __half* __restrict__ Wmh, __half* __restrict__ Wml,
                             __half* __restrict__ W1h, __half* __restrict__ W1l,
                             float* __restrict__ bp)
{
    int idx = blockIdx.x * blockDim.x + threadIdx.x;
    if (idx >= NPACK * DD) return;
    int c = idx >> 10;          // packed column (d*4 + gate)
    int k = idx & 1023;
    int d = c >> 2, g = c & 3;
    const int TD = 3 * DD;
    float vm, v1;
    if (g == 0)      { float u = U[(size_t)k * TD + d];            vm = W[(size_t)k * TD + d] + u;            v1 = u; }
    else if (g == 1) { float u = U[(size_t)k * TD + DD + d];       vm = W[(size_t)k * TD + DD + d] + u;       v1 = u; }
    else if (g == 2) { vm = W[(size_t)k * TD + 2 * DD + d];        v1 = 0.0f; }
    else             { float u = U[(size_t)k * TD + 2 * DD + d];   vm = u;    v1 = u; }
    __half h1 = __float2half_rn(vm);
    Wmh[idx] = h1;
    Wml[idx] = __float2half_rn((vm - __half2float(h1)) * 2048.0f);
    __half h2 = __float2half_rn(v1);
    W1h[idx] = h2;
    W1l[idx] = __float2half_rn((v1 - __half2float(h2)) * 2048.0f);
    if (k == 0)
        bp[c] = (g == 0) ? b[d] : (g == 1) ? b[DD + d] : (g == 2) ? b[2 * DD + d] : 0.0f;
}

__global__ void init_h(const float* __restrict__ x,
                       __half* __restrict__ h16, float* __restrict__ hstate)
{
    int i = blockIdx.x * blockDim.x + threadIdx.x;
    if (i < BATCH * DD) {
        float v = x[i];
        h16[i] = __float2half_rn(v);
        hstate[i] = v;
    }
}

// ---------------- launch -----------------------------------------------------
extern "C" void kernel_launch(void* const* d_in, const int* in_sizes, int n_in,
                              void* d_out, int out_size)
{
    const float* x = (const float*)d_in[0];
    const float* W = (const float*)d_in[1];
    const float* U = (const float*)d_in[2];
    const float* b = (const float*)d_in[3];
    float* out = (float*)d_out;

    void *pWmh, *pWml, *pW1h, *pW1l, *pH16, *pHst, *pBias;
    cudaGetSymbolAddress(&pWmh, g_Wmh);
    cudaGetSymbolAddress(&pWml, g_Wml);
    cudaGetSymbolAddress(&pW1h, g_W1h);
    cudaGetSymbolAddress(&pW1l, g_W1l);
    cudaGetSymbolAddress(&pH16, g_h16);
    cudaGetSymbolAddress(&pHst, g_hstate);
    cudaGetSymbolAddress(&pBias, g_bias);
    __half* Wmh = (__half*)pWmh;
    __half* Wml = (__half*)pWml;
    __half* W1h = (__half*)pW1h;
    __half* W1l = (__half*)pW1l;
    __half* H16 = (__half*)pH16;     // [2][BATCH*DD]
    float* Hst = (float*)pHst;
    float* Bias = (float*)pBias;

    cudaFuncSetAttribute(gru_step_kernel, cudaFuncAttributeMaxDynamicSharedMemorySize, SMEM_DYN);

    pack_weights<<<(NPACK * DD + 255) / 256, 256>>>(W, U, b, Wmh, Wml, W1h, W1l, Bias);
    init_h<<<(BATCH * DD + 255) / 256, 256>>>(x, H16, Hst);

    dim3 grid(32, 4);
    for (int t = 0; t < TSTEPS; ++t) {
        const __half* wh = (t == 0) ? W1h : Wmh;
        const __half* wl = (t == 0) ? W1l : Wml;
        int bin = t & 1, bout = (t + 1) & 1;
        gru_step_kernel<<<grid, 512, SMEM_DYN>>>(
            wh, wl,
            H16 + (size_t)bin * (BATCH * DD), H16 + (size_t)bout * (BATCH * DD),
            Hst, Bias, out, t);
    }
    (void)in_sizes; (void)n_in; (void)out_size;
}